// round 1
// baseline (speedup 1.0000x reference)
#include <cuda_runtime.h>
#include <cuda_bf16.h>
#include <cstdint>

// ---------------------------------------------------------------------------
// MultiHeadAttention  B=2 L=2048 D=1024 H=16 Dk=64
// Pipeline: QKV proj (tf32 mma) -> flash attention (tf32 mma + online softmax)
//           -> out proj (tf32 mma). fp32 accumulation everywhere.
// ---------------------------------------------------------------------------

#define B_  2
#define L_  2048
#define D_  1024
#define H_  16
#define DK_ 64
#define M_  (B_ * L_)          // 4096 rows

// Scratch (device globals: allocation-free)
__device__ float g_Q[B_ * H_ * L_ * DK_];   // [b][h][l][d]
__device__ float g_K[B_ * H_ * L_ * DK_];
__device__ float g_V[B_ * H_ * L_ * DK_];
__device__ float g_O[M_ * D_];              // [b*l][h*64+d]

// ---- helpers ---------------------------------------------------------------

__device__ __forceinline__ float tf32f(float x) {
    uint32_t u;
    asm("cvt.rna.tf32.f32 %0, %1;" : "=r"(u) : "f"(x));
    return __uint_as_float(u);
}
__device__ __forceinline__ uint32_t fu(float x) { return __float_as_uint(x); }

// D = A(16x8,row) * B(8x8,col) + D, tf32 in, f32 acc
__device__ __forceinline__ void mma8(float* c, const uint32_t* a, const uint32_t* b) {
    asm volatile(
        "mma.sync.aligned.m16n8k8.row.col.f32.tf32.tf32.f32 "
        "{%0,%1,%2,%3}, {%4,%5,%6,%7}, {%8,%9}, {%0,%1,%2,%3};\n"
        : "+f"(c[0]), "+f"(c[1]), "+f"(c[2]), "+f"(c[3])
        : "r"(a[0]), "r"(a[1]), "r"(a[2]), "r"(a[3]), "r"(b[0]), "r"(b[1]));
}

// ---- GEMM: C[M x N] = A[M x K] * W[K x N] + bias ---------------------------
// Block tile 128x64, BK=32, 256 threads = 8 warps in 4(m) x 2(n), warp 32x32.
// transHead: write into [b][h][l][d] scratch layout for Q/K/V.

#define AP 36   // A smem pitch: bank = (4r + c) % 32 -> conflict-free frags
#define BP 72   // B smem pitch: bank = (8k + n) % 32 -> conflict-free frags

__global__ __launch_bounds__(256) void gemm_tf32(
    const float* __restrict__ A, const float* __restrict__ W,
    const float* __restrict__ bias, float* __restrict__ C,
    int K, int N, int transHead)
{
    __shared__ float As[128 * AP];   // 18432 B
    __shared__ float Bs[32 * BP];    //  9216 B

    const int tid  = threadIdx.x;
    const int lane = tid & 31, wid = tid >> 5;
    const int wy = wid >> 1, wx = wid & 1;       // warp grid 4 x 2
    const int g = lane >> 2, tg = lane & 3;

    const int m0 = blockIdx.y * 128;
    const int n0 = blockIdx.x * 64;

    float acc[2][4][4];
#pragma unroll
    for (int mi = 0; mi < 2; mi++)
#pragma unroll
        for (int ni = 0; ni < 4; ni++)
#pragma unroll
            for (int j = 0; j < 4; j++) acc[mi][ni][j] = 0.f;

    for (int kt = 0; kt < K; kt += 32) {
        // load A tile: 128x32 = 1024 float4
#pragma unroll
        for (int i = tid; i < 1024; i += 256) {
            int r = i >> 3, c4 = (i & 7) << 2;
            float4 v = *(const float4*)(A + (size_t)(m0 + r) * K + kt + c4);
            float* d = &As[r * AP + c4];
            d[0] = tf32f(v.x); d[1] = tf32f(v.y); d[2] = tf32f(v.z); d[3] = tf32f(v.w);
        }
        // load B tile: 32x64 = 512 float4
#pragma unroll
        for (int i = tid; i < 512; i += 256) {
            int r = i >> 4, c4 = (i & 15) << 2;
            float4 v = *(const float4*)(W + (size_t)(kt + r) * N + n0 + c4);
            float* d = &Bs[r * BP + c4];
            d[0] = tf32f(v.x); d[1] = tf32f(v.y); d[2] = tf32f(v.z); d[3] = tf32f(v.w);
        }
        __syncthreads();

#pragma unroll
        for (int ks = 0; ks < 4; ks++) {
            const int k0 = ks * 8;
            uint32_t a[2][4];
#pragma unroll
            for (int mi = 0; mi < 2; mi++) {
                int r0 = wy * 32 + mi * 16;
                a[mi][0] = fu(As[(r0 + g) * AP + k0 + tg]);
                a[mi][1] = fu(As[(r0 + g + 8) * AP + k0 + tg]);
                a[mi][2] = fu(As[(r0 + g) * AP + k0 + tg + 4]);
                a[mi][3] = fu(As[(r0 + g + 8) * AP + k0 + tg + 4]);
            }
            uint32_t b[4][2];
#pragma unroll
            for (int ni = 0; ni < 4; ni++) {
                int c0 = wx * 32 + ni * 8;
                b[ni][0] = fu(Bs[(k0 + tg) * BP + c0 + g]);
                b[ni][1] = fu(Bs[(k0 + tg + 4) * BP + c0 + g]);
            }
#pragma unroll
            for (int mi = 0; mi < 2; mi++)
#pragma unroll
                for (int ni = 0; ni < 4; ni++)
                    mma8(acc[mi][ni], a[mi], b[ni]);
        }
        __syncthreads();
    }

    // epilogue + bias
#pragma unroll
    for (int mi = 0; mi < 2; mi++) {
        int r1 = m0 + wy * 32 + mi * 16 + g;
        int r2 = r1 + 8;
#pragma unroll
        for (int ni = 0; ni < 4; ni++) {
            int c0 = n0 + wx * 32 + ni * 8 + 2 * tg;
            float b0 = bias[c0], b1 = bias[c0 + 1];
            float v00 = acc[mi][ni][0] + b0, v01 = acc[mi][ni][1] + b1;
            float v10 = acc[mi][ni][2] + b0, v11 = acc[mi][ni][3] + b1;
            if (transHead) {
                // dst[((b*H + h)*L + l)*64 + d]
                int b_1 = r1 >> 11, l1 = r1 & 2047;
                int b_2 = r2 >> 11, l2 = r2 & 2047;
                int h = c0 >> 6, d = c0 & 63;
                C[((size_t)(b_1 * H_ + h) * L_ + l1) * DK_ + d]     = v00;
                C[((size_t)(b_1 * H_ + h) * L_ + l1) * DK_ + d + 1] = v01;
                C[((size_t)(b_2 * H_ + h) * L_ + l2) * DK_ + d]     = v10;
                C[((size_t)(b_2 * H_ + h) * L_ + l2) * DK_ + d + 1] = v11;
            } else {
                C[(size_t)r1 * N + c0]     = v00;
                C[(size_t)r1 * N + c0 + 1] = v01;
                C[(size_t)r2 * N + c0]     = v10;
                C[(size_t)r2 * N + c0 + 1] = v11;
            }
        }
    }
}

// ---- Flash attention -------------------------------------------------------
// One block per (bh, q-tile of 64). 256 threads = 8 warps in 2(m) x 4(n),
// warp tile 32x16 over the 64x64 S/O tiles. K/V tiles of 64 streamed.

#define QP 68   // pitch for Qs/Ks/Ps (bank = 4g+tg, conflict-free)
#define VP 72   // pitch for Vs     (bank = 8tg+g, conflict-free)

__global__ __launch_bounds__(256) void attn_kernel(
    const float* __restrict__ Qg, const float* __restrict__ Kg,
    const float* __restrict__ Vg, float* __restrict__ Og)
{
    extern __shared__ float sm[];
    float* Qs   = sm;                 // [64][QP]
    float* Ks   = Qs + 64 * QP;       // [64][QP]
    float* Vs   = Ks + 64 * QP;       // [64][VP]
    float* Ps   = Vs + 64 * VP;       // [64][QP]
    float* mrow = Ps + 64 * QP;       // [64]
    float* lrow = mrow + 64;          // [64]
    float* crow = lrow + 64;          // [64]

    const int tid  = threadIdx.x;
    const int lane = tid & 31, wid = tid >> 5;
    const int wy = wid >> 2, wx = wid & 3;       // warp grid 2 x 4
    const int g = lane >> 2, tg = lane & 3;

    const int bh = blockIdx.y;                   // b*16 + h
    const int qt = blockIdx.x;
    const float* Qb = Qg + ((size_t)bh * L_ + qt * 64) * DK_;
    const float* Kh = Kg + (size_t)bh * L_ * DK_;
    const float* Vh = Vg + (size_t)bh * L_ * DK_;

    // load Q tile (scaled by Dk^-0.5 = 0.125, exact), convert to tf32
#pragma unroll
    for (int i = tid; i < 1024; i += 256) {
        int r = i >> 4, c4 = (i & 15) << 2;
        float4 v = *(const float4*)(Qb + r * DK_ + c4);
        float* d = &Qs[r * QP + c4];
        d[0] = tf32f(v.x * 0.125f); d[1] = tf32f(v.y * 0.125f);
        d[2] = tf32f(v.z * 0.125f); d[3] = tf32f(v.w * 0.125f);
    }
    if (tid < 64) { mrow[tid] = -1e30f; lrow[tid] = 0.f; }

    float o[2][2][4];
#pragma unroll
    for (int mi = 0; mi < 2; mi++)
#pragma unroll
        for (int ni = 0; ni < 2; ni++)
#pragma unroll
            for (int j = 0; j < 4; j++) o[mi][ni][j] = 0.f;

    for (int kt = 0; kt < L_ / 64; kt++) {
        __syncthreads();   // previous iter consumers done before overwrite
        const float* Kt = Kh + (size_t)kt * 64 * DK_;
        const float* Vt = Vh + (size_t)kt * 64 * DK_;
#pragma unroll
        for (int i = tid; i < 1024; i += 256) {
            int r = i >> 4, c4 = (i & 15) << 2;
            float4 kv = *(const float4*)(Kt + r * DK_ + c4);
            float* dk = &Ks[r * QP + c4];
            dk[0] = tf32f(kv.x); dk[1] = tf32f(kv.y); dk[2] = tf32f(kv.z); dk[3] = tf32f(kv.w);
            float4 vv = *(const float4*)(Vt + r * DK_ + c4);
            float* dv = &Vs[r * VP + c4];
            dv[0] = tf32f(vv.x); dv[1] = tf32f(vv.y); dv[2] = tf32f(vv.z); dv[3] = tf32f(vv.w);
        }
        __syncthreads();

        // S = Q * K^T  (64x64), warp computes rows [wy*32,+32) x cols [wx*16,+16)
        float s[2][2][4];
#pragma unroll
        for (int mi = 0; mi < 2; mi++)
#pragma unroll
            for (int ni = 0; ni < 2; ni++)
#pragma unroll
                for (int j = 0; j < 4; j++) s[mi][ni][j] = 0.f;

#pragma unroll
        for (int ks = 0; ks < 8; ks++) {
            const int k0 = ks * 8;
            uint32_t a[2][4];
#pragma unroll
            for (int mi = 0; mi < 2; mi++) {
                int r0 = wy * 32 + mi * 16;
                a[mi][0] = fu(Qs[(r0 + g) * QP + k0 + tg]);
                a[mi][1] = fu(Qs[(r0 + g + 8) * QP + k0 + tg]);
                a[mi][2] = fu(Qs[(r0 + g) * QP + k0 + tg + 4]);
                a[mi][3] = fu(Qs[(r0 + g + 8) * QP + k0 + tg + 4]);
            }
            uint32_t b[2][2];
#pragma unroll
            for (int ni = 0; ni < 2; ni++) {
                int c0 = wx * 16 + ni * 8;
                b[ni][0] = fu(Ks[(c0 + g) * QP + k0 + tg]);     // K[j][d]
                b[ni][1] = fu(Ks[(c0 + g) * QP + k0 + tg + 4]);
            }
#pragma unroll
            for (int mi = 0; mi < 2; mi++)
#pragma unroll
                for (int ni = 0; ni < 2; ni++)
                    mma8(s[mi][ni], a[mi], b[ni]);
        }

        // S fragments -> Ps
#pragma unroll
        for (int mi = 0; mi < 2; mi++) {
            int r0 = wy * 32 + mi * 16;
#pragma unroll
            for (int ni = 0; ni < 2; ni++) {
                int c0 = wx * 16 + ni * 8 + 2 * tg;
                Ps[(r0 + g) * QP + c0]         = s[mi][ni][0];
                Ps[(r0 + g) * QP + c0 + 1]     = s[mi][ni][1];
                Ps[(r0 + g + 8) * QP + c0]     = s[mi][ni][2];
                Ps[(r0 + g + 8) * QP + c0 + 1] = s[mi][ni][3];
            }
        }
        __syncthreads();

        // softmax phase A: row max + correction factor
        if (tid < 64) {
            float mold = mrow[tid];
            float mx = mold;
            const float* pr = Ps + tid * QP;
#pragma unroll 8
            for (int j = 0; j < 64; j++) mx = fmaxf(mx, pr[j]);
            crow[tid] = __expf(mold - mx);
            mrow[tid] = mx;
        }
        __syncthreads();
        // phase B: elementwise exp (all threads), store tf32(p)
#pragma unroll
        for (int i = tid; i < 4096; i += 256) {
            int r = i >> 6, j = i & 63;
            float p = __expf(Ps[r * QP + j] - mrow[r]);
            Ps[r * QP + j] = tf32f(p);
        }
        __syncthreads();
        // phase C: row sums -> l update (runs concurrently with PV below)
        if (tid < 64) {
            float ssum = 0.f;
            const float* pr = Ps + tid * QP;
#pragma unroll 8
            for (int j = 0; j < 64; j++) ssum += pr[j];
            lrow[tid] = lrow[tid] * crow[tid] + ssum;
        }

        // rescale O accumulators by crow
#pragma unroll
        for (int mi = 0; mi < 2; mi++) {
            int r0 = wy * 32 + mi * 16;
            float c1 = crow[r0 + g];
            float c2 = crow[r0 + g + 8];
#pragma unroll
            for (int ni = 0; ni < 2; ni++) {
                o[mi][ni][0] *= c1; o[mi][ni][1] *= c1;
                o[mi][ni][2] *= c2; o[mi][ni][3] *= c2;
            }
        }

        // O += P * V
#pragma unroll
        for (int ks = 0; ks < 8; ks++) {
            const int k0 = ks * 8;
            uint32_t a[2][4];
#pragma unroll
            for (int mi = 0; mi < 2; mi++) {
                int r0 = wy * 32 + mi * 16;
                a[mi][0] = fu(Ps[(r0 + g) * QP + k0 + tg]);
                a[mi][1] = fu(Ps[(r0 + g + 8) * QP + k0 + tg]);
                a[mi][2] = fu(Ps[(r0 + g) * QP + k0 + tg + 4]);
                a[mi][3] = fu(Ps[(r0 + g + 8) * QP + k0 + tg + 4]);
            }
            uint32_t b[2][2];
#pragma unroll
            for (int ni = 0; ni < 2; ni++) {
                int c0 = wx * 16 + ni * 8;
                b[ni][0] = fu(Vs[(k0 + tg) * VP + c0 + g]);      // V[j][c]
                b[ni][1] = fu(Vs[(k0 + tg + 4) * VP + c0 + g]);
            }
#pragma unroll
            for (int mi = 0; mi < 2; mi++)
#pragma unroll
                for (int ni = 0; ni < 2; ni++)
                    mma8(o[mi][ni], a[mi], b[ni]);
        }
    }
    __syncthreads();   // lrow final

    // epilogue: divide by l, write O scratch in [b*l][h*64+d] layout
    const int b = bh >> 4, h = bh & 15;
#pragma unroll
    for (int mi = 0; mi < 2; mi++) {
        int r0 = wy * 32 + mi * 16;
        float inv1 = 1.f / lrow[r0 + g];
        float inv2 = 1.f / lrow[r0 + g + 8];
        int l1 = qt * 64 + r0 + g;
        int l2 = l1 + 8;
#pragma unroll
        for (int ni = 0; ni < 2; ni++) {
            int c = wx * 16 + ni * 8 + 2 * tg;
            size_t i1 = ((size_t)(b * L_ + l1) * D_) + h * DK_ + c;
            size_t i2 = ((size_t)(b * L_ + l2) * D_) + h * DK_ + c;
            Og[i1]     = o[mi][ni][0] * inv1;
            Og[i1 + 1] = o[mi][ni][1] * inv1;
            Og[i2]     = o[mi][ni][2] * inv2;
            Og[i2 + 1] = o[mi][ni][3] * inv2;
        }
    }
}

// ---------------------------------------------------------------------------

extern "C" void kernel_launch(void* const* d_in, const int* in_sizes, int n_in,
                              void* d_out, int out_size)
{
    const float* x  = (const float*)d_in[0];
    const float* wq = (const float*)d_in[1];
    const float* bq = (const float*)d_in[2];
    const float* wk = (const float*)d_in[3];
    const float* bk = (const float*)d_in[4];
    const float* wv = (const float*)d_in[5];
    const float* bv = (const float*)d_in[6];
    const float* wo = (const float*)d_in[7];
    const float* bo = (const float*)d_in[8];
    float* out = (float*)d_out;

    void *pQ, *pK, *pV, *pO;
    cudaGetSymbolAddress(&pQ, g_Q);
    cudaGetSymbolAddress(&pK, g_K);
    cudaGetSymbolAddress(&pV, g_V);
    cudaGetSymbolAddress(&pO, g_O);

    const int smem_attn = (64 * QP * 3 + 64 * VP + 3 * 64) * sizeof(float);
    cudaFuncSetAttribute(attn_kernel, cudaFuncAttributeMaxDynamicSharedMemorySize, smem_attn);

    dim3 gg(D_ / 64, M_ / 128);   // (16, 32)
    gemm_tf32<<<gg, 256>>>(x, wq, bq, (float*)pQ, D_, D_, 1);
    gemm_tf32<<<gg, 256>>>(x, wk, bk, (float*)pK, D_, D_, 1);
    gemm_tf32<<<gg, 256>>>(x, wv, bv, (float*)pV, D_, D_, 1);

    attn_kernel<<<dim3(L_ / 64, B_ * H_), 256, smem_attn>>>(
        (const float*)pQ, (const float*)pK, (const float*)pV, (float*)pO);

    gemm_tf32<<<gg, 256>>>((const float*)pO, wo, bo, out, D_, D_, 0);
}

// round 3
// speedup vs baseline: 1.5959x; 1.5959x over previous
#include <cuda_runtime.h>
#include <cuda_fp16.h>
#include <cstdint>

// ---------------------------------------------------------------------------
// MultiHeadAttention  B=2 L=2048 D=1024 H=16 Dk=64
// QKV proj (tf32 mma, fp16 out) -> FA2-style fp16 attention (m16n8k16,
// ldmatrix, register softmax, cp.async double buffer) -> out proj (tf32 mma).
// ---------------------------------------------------------------------------

#define B_  2
#define L_  2048
#define D_  1024
#define H_  16
#define DK_ 64
#define M_  (B_ * L_)          // 4096 rows

// fp16 scratch (device globals: allocation-free)
__device__ __half g_Q[B_ * H_ * L_ * DK_];   // [b][h][l][d], pre-scaled by 0.125*log2e
__device__ __half g_K[B_ * H_ * L_ * DK_];
__device__ __half g_V[B_ * H_ * L_ * DK_];
__device__ __half g_O[M_ * D_];              // [b*l][h*64+d]

// ---- helpers ---------------------------------------------------------------

__device__ __forceinline__ float tf32f(float x) {
    uint32_t u;
    asm("cvt.rna.tf32.f32 %0, %1;" : "=r"(u) : "f"(x));
    return __uint_as_float(u);
}
__device__ __forceinline__ uint32_t fu(float x) { return __float_as_uint(x); }

__device__ __forceinline__ float ex2(float x) {
    float y; asm("ex2.approx.f32 %0, %1;" : "=f"(y) : "f"(x)); return y;
}
__device__ __forceinline__ uint32_t h2u(__half2 h) {
    return *reinterpret_cast<uint32_t*>(&h);
}
__device__ __forceinline__ uint32_t cvta_s(const void* p) {
    return (uint32_t)__cvta_generic_to_shared(p);
}
__device__ __forceinline__ void cpa16(uint32_t dst, const void* src) {
    asm volatile("cp.async.cg.shared.global [%0], [%1], 16;\n" :: "r"(dst), "l"(src));
}
__device__ __forceinline__ void cpcommit() { asm volatile("cp.async.commit_group;\n"); }
__device__ __forceinline__ void cpwait0()  { asm volatile("cp.async.wait_group 0;\n"); }

__device__ __forceinline__ void ldm4(uint32_t& r0, uint32_t& r1, uint32_t& r2, uint32_t& r3, uint32_t addr) {
    asm volatile("ldmatrix.sync.aligned.m8n8.x4.shared.b16 {%0,%1,%2,%3}, [%4];\n"
        : "=r"(r0), "=r"(r1), "=r"(r2), "=r"(r3) : "r"(addr));
}
__device__ __forceinline__ void ldm4t(uint32_t& r0, uint32_t& r1, uint32_t& r2, uint32_t& r3, uint32_t addr) {
    asm volatile("ldmatrix.sync.aligned.m8n8.x4.trans.shared.b16 {%0,%1,%2,%3}, [%4];\n"
        : "=r"(r0), "=r"(r1), "=r"(r2), "=r"(r3) : "r"(addr));
}

// fp16 mma, fp32 accum
__device__ __forceinline__ void mma16(float* c, uint32_t a0, uint32_t a1, uint32_t a2, uint32_t a3,
                                      uint32_t b0, uint32_t b1) {
    asm volatile(
        "mma.sync.aligned.m16n8k16.row.col.f32.f16.f16.f32 "
        "{%0,%1,%2,%3}, {%4,%5,%6,%7}, {%8,%9}, {%0,%1,%2,%3};\n"
        : "+f"(c[0]), "+f"(c[1]), "+f"(c[2]), "+f"(c[3])
        : "r"(a0), "r"(a1), "r"(a2), "r"(a3), "r"(b0), "r"(b1));
}

// tf32 mma (GEMMs)
__device__ __forceinline__ void mma8(float* c, const uint32_t* a, const uint32_t* b) {
    asm volatile(
        "mma.sync.aligned.m16n8k8.row.col.f32.tf32.tf32.f32 "
        "{%0,%1,%2,%3}, {%4,%5,%6,%7}, {%8,%9}, {%0,%1,%2,%3};\n"
        : "+f"(c[0]), "+f"(c[1]), "+f"(c[2]), "+f"(c[3])
        : "r"(a[0]), "r"(a[1]), "r"(a[2]), "r"(a[3]), "r"(b[0]), "r"(b[1]));
}

// ---- GEMM: C[M x N] = (A[M x K] * W[K x N] + bias) * oscale ----------------
// Block tile 128x64, BK=32, 256 threads. aHalf: A is fp16. transHead: write
// fp16 into [b][h][l][d] scratch.

#define AP 36
#define BP 72

__global__ __launch_bounds__(256) void gemm_tf32(
    const void* __restrict__ Av, const float* __restrict__ W,
    const float* __restrict__ bias, void* __restrict__ Cv,
    int K, int N, int transHead, int aHalf, float oscale)
{
    __shared__ float As[128 * AP];
    __shared__ float Bs[32 * BP];

    const int tid  = threadIdx.x;
    const int lane = tid & 31, wid = tid >> 5;
    const int wy = wid >> 1, wx = wid & 1;
    const int g = lane >> 2, tg = lane & 3;

    const int m0 = blockIdx.y * 128;
    const int n0 = blockIdx.x * 64;

    float acc[2][4][4];
#pragma unroll
    for (int mi = 0; mi < 2; mi++)
#pragma unroll
        for (int ni = 0; ni < 4; ni++)
#pragma unroll
            for (int j = 0; j < 4; j++) acc[mi][ni][j] = 0.f;

    for (int kt = 0; kt < K; kt += 32) {
        if (aHalf) {
            const __half* A = (const __half*)Av;
#pragma unroll
            for (int i = tid; i < 512; i += 256) {
                int r = i >> 2, c8 = (i & 3) << 3;
                float4 v = *(const float4*)(A + (size_t)(m0 + r) * K + kt + c8);
                const __half2* hp = (const __half2*)&v;
                float* d = &As[r * AP + c8];
#pragma unroll
                for (int t = 0; t < 4; t++) {
                    float2 f = __half22float2(hp[t]);
                    d[2*t] = tf32f(f.x); d[2*t+1] = tf32f(f.y);
                }
            }
        } else {
            const float* A = (const float*)Av;
#pragma unroll
            for (int i = tid; i < 1024; i += 256) {
                int r = i >> 3, c4 = (i & 7) << 2;
                float4 v = *(const float4*)(A + (size_t)(m0 + r) * K + kt + c4);
                float* d = &As[r * AP + c4];
                d[0] = tf32f(v.x); d[1] = tf32f(v.y); d[2] = tf32f(v.z); d[3] = tf32f(v.w);
            }
        }
#pragma unroll
        for (int i = tid; i < 512; i += 256) {
            int r = i >> 4, c4 = (i & 15) << 2;
            float4 v = *(const float4*)(W + (size_t)(kt + r) * N + n0 + c4);
            float* d = &Bs[r * BP + c4];
            d[0] = tf32f(v.x); d[1] = tf32f(v.y); d[2] = tf32f(v.z); d[3] = tf32f(v.w);
        }
        __syncthreads();

#pragma unroll
        for (int ks = 0; ks < 4; ks++) {
            const int k0 = ks * 8;
            uint32_t a[2][4];
#pragma unroll
            for (int mi = 0; mi < 2; mi++) {
                int r0 = wy * 32 + mi * 16;
                a[mi][0] = fu(As[(r0 + g) * AP + k0 + tg]);
                a[mi][1] = fu(As[(r0 + g + 8) * AP + k0 + tg]);
                a[mi][2] = fu(As[(r0 + g) * AP + k0 + tg + 4]);
                a[mi][3] = fu(As[(r0 + g + 8) * AP + k0 + tg + 4]);
            }
            uint32_t b[4][2];
#pragma unroll
            for (int ni = 0; ni < 4; ni++) {
                int c0 = wx * 32 + ni * 8;
                b[ni][0] = fu(Bs[(k0 + tg) * BP + c0 + g]);
                b[ni][1] = fu(Bs[(k0 + tg + 4) * BP + c0 + g]);
            }
#pragma unroll
            for (int mi = 0; mi < 2; mi++)
#pragma unroll
                for (int ni = 0; ni < 4; ni++)
                    mma8(acc[mi][ni], a[mi], b[ni]);
        }
        __syncthreads();
    }

#pragma unroll
    for (int mi = 0; mi < 2; mi++) {
        int r1 = m0 + wy * 32 + mi * 16 + g;
        int r2 = r1 + 8;
#pragma unroll
        for (int ni = 0; ni < 4; ni++) {
            int c0 = n0 + wx * 32 + ni * 8 + 2 * tg;
            float b0 = bias[c0], b1 = bias[c0 + 1];
            float v00 = (acc[mi][ni][0] + b0) * oscale, v01 = (acc[mi][ni][1] + b1) * oscale;
            float v10 = (acc[mi][ni][2] + b0) * oscale, v11 = (acc[mi][ni][3] + b1) * oscale;
            if (transHead) {
                __half* C = (__half*)Cv;
                int b_1 = r1 >> 11, l1 = r1 & 2047;
                int b_2 = r2 >> 11, l2 = r2 & 2047;
                int h = c0 >> 6, d = c0 & 63;
                *(__half2*)(C + ((size_t)(b_1 * H_ + h) * L_ + l1) * DK_ + d) = __floats2half2_rn(v00, v01);
                *(__half2*)(C + ((size_t)(b_2 * H_ + h) * L_ + l2) * DK_ + d) = __floats2half2_rn(v10, v11);
            } else {
                float* C = (float*)Cv;
                C[(size_t)r1 * N + c0]     = v00;
                C[(size_t)r1 * N + c0 + 1] = v01;
                C[(size_t)r2 * N + c0]     = v10;
                C[(size_t)r2 * N + c0 + 1] = v11;
            }
        }
    }
}

// ---- Flash attention (fp16, FA2 register softmax) --------------------------
// Block: 256 threads = 8 warps; Q tile 128 rows (warp w owns rows 16w..16w+15,
// full 64 cols). K/V tiles of 64 rows, cp.async double-buffered.
// Smem fp16 rows of 64 halves = 8 chunks of 16B, XOR-swizzled: chunk' = c ^ (r&7).

__global__ __launch_bounds__(256) void attn_fp16(
    const __half* __restrict__ Qg, const __half* __restrict__ Kg,
    const __half* __restrict__ Vg, __half* __restrict__ Og)
{
    extern __shared__ __align__(16) __half sm[];
    __half* Qs  = sm;             // 128x64 = 8192 halves
    __half* KsB = sm + 8192;      // 2 x 64x64
    __half* VsB = sm + 16384;     // 2 x 64x64

    const int tid = threadIdx.x, lane = tid & 31, w = tid >> 5;
    const int bh = blockIdx.y, qt = blockIdx.x;
    const __half* Qb = Qg + ((size_t)bh * L_ + qt * 128) * DK_;
    const __half* Kh = Kg + (size_t)bh * L_ * DK_;
    const __half* Vh = Vg + (size_t)bh * L_ * DK_;

    const uint32_t qsb = cvta_s(Qs), ksb = cvta_s(KsB), vsb = cvta_s(VsB);

    // Q: 128 rows x 8 chunks
#pragma unroll
    for (int i = tid; i < 1024; i += 256) {
        int r = i >> 3, c = i & 7;
        cpa16(qsb + (r * 8 + (c ^ (r & 7))) * 16, Qb + r * 64 + c * 8);
    }
    // K0 / V0 into buf 0
#pragma unroll
    for (int i = tid; i < 512; i += 256) {
        int r = i >> 3, c = i & 7;
        uint32_t so = (r * 8 + (c ^ (r & 7))) * 16;
        cpa16(ksb + so, Kh + r * 64 + c * 8);
        cpa16(vsb + so, Vh + r * 64 + c * 8);
    }
    cpcommit();

    float m0 = -1e30f, m1 = -1e30f, l0 = 0.f, l1 = 0.f;
    float o[8][4];
#pragma unroll
    for (int i = 0; i < 8; i++)
#pragma unroll
        for (int j = 0; j < 4; j++) o[i][j] = 0.f;

    const int rlo = lane & 15, hi = lane >> 4;
    const int qrow = w * 16 + rlo;
    const uint32_t qrowb = qsb + qrow * 128;
    const int qsw = qrow & 7;

    for (int kt = 0; kt < L_ / 64; kt++) {
        cpwait0();
        __syncthreads();
        if (kt + 1 < L_ / 64) {
            int buf = (kt + 1) & 1;
            const __half* Kt = Kh + (size_t)(kt + 1) * 64 * DK_;
            const __half* Vt = Vh + (size_t)(kt + 1) * 64 * DK_;
            uint32_t kd = ksb + buf * 8192, vd = vsb + buf * 8192;
#pragma unroll
            for (int i = tid; i < 512; i += 256) {
                int r = i >> 3, c = i & 7;
                uint32_t so = (r * 8 + (c ^ (r & 7))) * 16;
                cpa16(kd + so, Kt + r * 64 + c * 8);
                cpa16(vd + so, Vt + r * 64 + c * 8);
            }
            cpcommit();
        }
        const int buf = kt & 1;
        const uint32_t kb = ksb + buf * 8192;
        const uint32_t vb = vsb + buf * 8192;

        // S = Q K^T : 16x64 per warp
        float s[8][4];
#pragma unroll
        for (int i = 0; i < 8; i++)
#pragma unroll
            for (int j = 0; j < 4; j++) s[i][j] = 0.f;

#pragma unroll
        for (int ks = 0; ks < 4; ks++) {
            uint32_t a0, a1, a2, a3;
            ldm4(a0, a1, a2, a3, qrowb + ((2 * ks + hi) ^ qsw) * 16);
#pragma unroll
            for (int nj = 0; nj < 4; nj++) {
                int kr = nj * 16 + rlo;
                uint32_t b0, b1, b2, b3;
                ldm4(b0, b1, b2, b3, kb + kr * 128 + ((2 * ks + hi) ^ (kr & 7)) * 16);
                mma16(s[2 * nj],     a0, a1, a2, a3, b0, b2);
                mma16(s[2 * nj + 1], a0, a1, a2, a3, b1, b3);
            }
        }

        // online softmax in registers (log2 domain; 0.125*log2e folded into Q)
        float ml0 = s[0][0], ml1 = s[0][2];
#pragma unroll
        for (int i = 0; i < 8; i++) {
            ml0 = fmaxf(ml0, fmaxf(s[i][0], s[i][1]));
            ml1 = fmaxf(ml1, fmaxf(s[i][2], s[i][3]));
        }
        ml0 = fmaxf(ml0, __shfl_xor_sync(0xffffffffu, ml0, 1));
        ml0 = fmaxf(ml0, __shfl_xor_sync(0xffffffffu, ml0, 2));
        ml1 = fmaxf(ml1, __shfl_xor_sync(0xffffffffu, ml1, 1));
        ml1 = fmaxf(ml1, __shfl_xor_sync(0xffffffffu, ml1, 2));
        float mn0 = fmaxf(m0, ml0), mn1 = fmaxf(m1, ml1);
        float c0 = ex2(m0 - mn0), c1 = ex2(m1 - mn1);
        m0 = mn0; m1 = mn1;
        float sum0 = 0.f, sum1 = 0.f;
#pragma unroll
        for (int i = 0; i < 8; i++) {
            s[i][0] = ex2(s[i][0] - mn0); s[i][1] = ex2(s[i][1] - mn0);
            s[i][2] = ex2(s[i][2] - mn1); s[i][3] = ex2(s[i][3] - mn1);
            sum0 += s[i][0] + s[i][1];
            sum1 += s[i][2] + s[i][3];
        }
        l0 = l0 * c0 + sum0;   // per-lane partial row sum; reduced at end
        l1 = l1 * c1 + sum1;
#pragma unroll
        for (int i = 0; i < 8; i++) {
            o[i][0] *= c0; o[i][1] *= c0; o[i][2] *= c1; o[i][3] *= c1;
        }

        // O += P V  (P: S C-frags map directly to A-frags)
#pragma unroll
        for (int ks = 0; ks < 4; ks++) {
            uint32_t a0 = h2u(__floats2half2_rn(s[2*ks][0],   s[2*ks][1]));
            uint32_t a1 = h2u(__floats2half2_rn(s[2*ks][2],   s[2*ks][3]));
            uint32_t a2 = h2u(__floats2half2_rn(s[2*ks+1][0], s[2*ks+1][1]));
            uint32_t a3 = h2u(__floats2half2_rn(s[2*ks+1][2], s[2*ks+1][3]));
            int vr = ks * 16 + rlo;
            uint32_t vrb = vb + vr * 128;
            int vsw = vr & 7;
#pragma unroll
            for (int nd = 0; nd < 4; nd++) {
                uint32_t v0, v1, v2, v3;
                ldm4t(v0, v1, v2, v3, vrb + ((2 * nd + hi) ^ vsw) * 16);
                mma16(o[2 * nd],     a0, a1, a2, a3, v0, v1);
                mma16(o[2 * nd + 1], a0, a1, a2, a3, v2, v3);
            }
        }
    }

    // finalize: reduce row sums across the quad, normalize, write fp16 O
    l0 += __shfl_xor_sync(0xffffffffu, l0, 1);
    l0 += __shfl_xor_sync(0xffffffffu, l0, 2);
    l1 += __shfl_xor_sync(0xffffffffu, l1, 1);
    l1 += __shfl_xor_sync(0xffffffffu, l1, 2);
    float inv0 = 1.f / l0, inv1 = 1.f / l1;

    const int g = lane >> 2, tg = lane & 3;
    const int b = bh >> 4, h = bh & 15;
    const int r0 = qt * 128 + w * 16 + g;
#pragma unroll
    for (int ni = 0; ni < 8; ni++) {
        int col = h * 64 + ni * 8 + 2 * tg;
        *(__half2*)(Og + (size_t)(b * L_ + r0) * D_ + col) =
            __floats2half2_rn(o[ni][0] * inv0, o[ni][1] * inv0);
        *(__half2*)(Og + (size_t)(b * L_ + r0 + 8) * D_ + col) =
            __floats2half2_rn(o[ni][2] * inv1, o[ni][3] * inv1);
    }
}

// ---------------------------------------------------------------------------

extern "C" void kernel_launch(void* const* d_in, const int* in_sizes, int n_in,
                              void* d_out, int out_size)
{
    const float* x  = (const float*)d_in[0];
    const float* wq = (const float*)d_in[1];
    const float* bq = (const float*)d_in[2];
    const float* wk = (const float*)d_in[3];
    const float* bk = (const float*)d_in[4];
    const float* wv = (const float*)d_in[5];
    const float* bv = (const float*)d_in[6];
    const float* wo = (const float*)d_in[7];
    const float* bo = (const float*)d_in[8];
    float* out = (float*)d_out;

    void *pQ, *pK, *pV, *pO;
    cudaGetSymbolAddress(&pQ, g_Q);
    cudaGetSymbolAddress(&pK, g_K);
    cudaGetSymbolAddress(&pV, g_V);
    cudaGetSymbolAddress(&pO, g_O);

    const int smem_attn = (128 * 64 + 2 * 64 * 64 + 2 * 64 * 64) * sizeof(__half); // 49152
    cudaFuncSetAttribute(attn_fp16, cudaFuncAttributeMaxDynamicSharedMemorySize, smem_attn);

    // 0.125 (Dk^-0.5) * log2(e): softmax done in base-2 domain
    const float qscale = 0.125f * 1.4426950408889634f;

    dim3 gg(D_ / 64, M_ / 128);   // (16, 32)
    gemm_tf32<<<gg, 256>>>(x, wq, bq, pQ, D_, D_, 1, 0, qscale);
    gemm_tf32<<<gg, 256>>>(x, wk, bk, pK, D_, D_, 1, 0, 1.0f);
    gemm_tf32<<<gg, 256>>>(x, wv, bv, pV, D_, D_, 1, 0, 1.0f);

    attn_fp16<<<dim3(L_ / 128, B_ * H_), 256, smem_attn>>>(
        (const __half*)pQ, (const __half*)pK, (const __half*)pV, (__half*)pO);

    gemm_tf32<<<gg, 256>>>(pO, wo, bo, out, D_, D_, 0, 1, 1.0f);
}

// round 4
// speedup vs baseline: 3.1344x; 1.9640x over previous
#include <cuda_runtime.h>
#include <cuda_fp16.h>
#include <cstdint>

// ---------------------------------------------------------------------------
// MultiHeadAttention  B=2 L=2048 D=1024 H=16 Dk=64
// fp32->fp16 convert pass -> QKV proj (fp16 m16n8k16 mma) -> FA2 fp16
// attention -> out proj (fp16 mma, fp32 out). fp32 accumulation everywhere.
// ---------------------------------------------------------------------------

#define B_  2
#define L_  2048
#define D_  1024
#define H_  16
#define DK_ 64
#define M_  (B_ * L_)          // 4096 rows

// fp16 scratch (device globals: allocation-free)
__device__ __half g_X [M_ * D_];             // x converted
__device__ __half g_Wq[D_ * D_];
__device__ __half g_Wk[D_ * D_];
__device__ __half g_Wv[D_ * D_];
__device__ __half g_Wo[D_ * D_];
__device__ __half g_Q[B_ * H_ * L_ * DK_];   // [b][h][l][d], pre-scaled by 0.125*log2e
__device__ __half g_K[B_ * H_ * L_ * DK_];
__device__ __half g_V[B_ * H_ * L_ * DK_];
__device__ __half g_O[M_ * D_];              // [b*l][h*64+d]

// ---- helpers ---------------------------------------------------------------

__device__ __forceinline__ float ex2(float x) {
    float y; asm("ex2.approx.f32 %0, %1;" : "=f"(y) : "f"(x)); return y;
}
__device__ __forceinline__ uint32_t h2u(__half2 h) {
    return *reinterpret_cast<uint32_t*>(&h);
}
__device__ __forceinline__ uint32_t cvta_s(const void* p) {
    return (uint32_t)__cvta_generic_to_shared(p);
}
__device__ __forceinline__ void cpa16(uint32_t dst, const void* src) {
    asm volatile("cp.async.cg.shared.global [%0], [%1], 16;\n" :: "r"(dst), "l"(src));
}
__device__ __forceinline__ void cpcommit() { asm volatile("cp.async.commit_group;\n"); }
__device__ __forceinline__ void cpwait0()  { asm volatile("cp.async.wait_group 0;\n"); }

__device__ __forceinline__ void ldm4(uint32_t& r0, uint32_t& r1, uint32_t& r2, uint32_t& r3, uint32_t addr) {
    asm volatile("ldmatrix.sync.aligned.m8n8.x4.shared.b16 {%0,%1,%2,%3}, [%4];\n"
        : "=r"(r0), "=r"(r1), "=r"(r2), "=r"(r3) : "r"(addr));
}
__device__ __forceinline__ void ldm4t(uint32_t& r0, uint32_t& r1, uint32_t& r2, uint32_t& r3, uint32_t addr) {
    asm volatile("ldmatrix.sync.aligned.m8n8.x4.trans.shared.b16 {%0,%1,%2,%3}, [%4];\n"
        : "=r"(r0), "=r"(r1), "=r"(r2), "=r"(r3) : "r"(addr));
}

// fp16 mma, fp32 accum
__device__ __forceinline__ void mma16(float* c, uint32_t a0, uint32_t a1, uint32_t a2, uint32_t a3,
                                      uint32_t b0, uint32_t b1) {
    asm volatile(
        "mma.sync.aligned.m16n8k16.row.col.f32.f16.f16.f32 "
        "{%0,%1,%2,%3}, {%4,%5,%6,%7}, {%8,%9}, {%0,%1,%2,%3};\n"
        : "+f"(c[0]), "+f"(c[1]), "+f"(c[2]), "+f"(c[3])
        : "r"(a0), "r"(a1), "r"(a2), "r"(a3), "r"(b0), "r"(b1));
}

// ---- fp32 -> fp16 converts -------------------------------------------------

__global__ __launch_bounds__(256) void cvt_x(const float* __restrict__ in, __half* __restrict__ out) {
    int i = (blockIdx.x * 256 + threadIdx.x) * 8;   // n = M_*D_ = 4M, divisible by 8
    float4 v0 = *(const float4*)(in + i);
    float4 v1 = *(const float4*)(in + i + 4);
    __half2 h[4] = { __floats2half2_rn(v0.x, v0.y), __floats2half2_rn(v0.z, v0.w),
                     __floats2half2_rn(v1.x, v1.y), __floats2half2_rn(v1.z, v1.w) };
    *(float4*)(out + i) = *(float4*)h;
}

__global__ __launch_bounds__(256) void cvt_w(
    const float* __restrict__ w0, const float* __restrict__ w1,
    const float* __restrict__ w2, const float* __restrict__ w3)
{
    const float* in; __half* out;
    switch (blockIdx.y) {
        case 0:  in = w0; out = g_Wq; break;
        case 1:  in = w1; out = g_Wk; break;
        case 2:  in = w2; out = g_Wv; break;
        default: in = w3; out = g_Wo; break;
    }
    int i = (blockIdx.x * 256 + threadIdx.x) * 8;   // n = 1M, divisible
    float4 v0 = *(const float4*)(in + i);
    float4 v1 = *(const float4*)(in + i + 4);
    __half2 h[4] = { __floats2half2_rn(v0.x, v0.y), __floats2half2_rn(v0.z, v0.w),
                     __floats2half2_rn(v1.x, v1.y), __floats2half2_rn(v1.z, v1.w) };
    *(float4*)(out + i) = *(float4*)h;
}

// ---- fp16 GEMM: C[M x N] = (A[M x K] * W[K x N] + bias) * oscale -----------
// Block tile 128x128, BK=32, 256 threads = 8 warps (2m x 4n), warp 64x32.
// A smem: 128 rows x 80B (32 halves + 8 pad) -> conflict-free ldmatrix.
// W smem: 32 rows x 256B, chunk swizzle c^(r&7) -> conflict-free ldm4t.
// Double-buffered cp.async.

#define GA_ST 10240           // A stage bytes (128*80)
#define GB_ST 8192            // B stage bytes (32*256)
#define G_SMEM (2 * (GA_ST + GB_ST))   // 36864

__global__ __launch_bounds__(256) void gemm_fp16(
    const __half* __restrict__ A, const __half* __restrict__ W,
    const float* __restrict__ bias, void* __restrict__ Cv,
    int K, int N, int transHead, float oscale)
{
    extern __shared__ __align__(16) char smem[];
    const uint32_t sb = cvta_s(smem);

    const int tid = threadIdx.x, lane = tid & 31, wid = tid >> 5;
    const int wy = wid >> 2, wx = wid & 3;          // 2 x 4 warp grid
    const int rlo = lane & 15, hi = lane >> 4;
    const int m0 = blockIdx.y * 128, n0 = blockIdx.x * 128;

    float acc[4][4][4];
#pragma unroll
    for (int mi = 0; mi < 4; mi++)
#pragma unroll
        for (int ni = 0; ni < 4; ni++)
#pragma unroll
            for (int j = 0; j < 4; j++) acc[mi][ni][j] = 0.f;

    auto load_tile = [&](int kt, int stage) {
        uint32_t ad = sb + stage * GA_ST;
        uint32_t bd = sb + 2 * GA_ST + stage * GB_ST;
#pragma unroll
        for (int it = 0; it < 2; it++) {
            int i = tid + it * 256;
            int r = i >> 2, c = i & 3;              // A: 128 rows x 4 chunks
            cpa16(ad + r * 80 + c * 16, A + (size_t)(m0 + r) * K + kt + c * 8);
        }
#pragma unroll
        for (int it = 0; it < 2; it++) {
            int i = tid + it * 256;
            int r = i >> 4, c = i & 15;             // B: 32 rows x 16 chunks
            cpa16(bd + r * 256 + (c ^ (r & 7)) * 16, W + (size_t)(kt + r) * N + n0 + c * 8);
        }
        cpcommit();
    };

    load_tile(0, 0);

    for (int kt = 0; kt < K; kt += 32) {
        cpwait0();
        __syncthreads();
        const int st = (kt >> 5) & 1;
        if (kt + 32 < K) load_tile(kt + 32, st ^ 1);

        const uint32_t ad = sb + st * GA_ST;
        const uint32_t bd = sb + 2 * GA_ST + st * GB_ST;

#pragma unroll
        for (int ks = 0; ks < 2; ks++) {
            uint32_t a[4][4];
#pragma unroll
            for (int mi = 0; mi < 4; mi++) {
                int r = wy * 64 + mi * 16 + rlo;
                ldm4(a[mi][0], a[mi][1], a[mi][2], a[mi][3],
                     ad + r * 80 + (2 * ks + hi) * 16);
            }
#pragma unroll
            for (int nj = 0; nj < 2; nj++) {
                int row = ks * 16 + rlo;
                int ch  = 2 * (wx * 2 + nj) + hi;
                uint32_t v0, v1, v2, v3;
                ldm4t(v0, v1, v2, v3, bd + row * 256 + ((ch ^ (row & 7)) * 16));
#pragma unroll
                for (int mi = 0; mi < 4; mi++) {
                    mma16(acc[mi][2 * nj],     a[mi][0], a[mi][1], a[mi][2], a[mi][3], v0, v1);
                    mma16(acc[mi][2 * nj + 1], a[mi][0], a[mi][1], a[mi][2], a[mi][3], v2, v3);
                }
            }
        }
    }

    // epilogue
    const int g = lane >> 2, tg = lane & 3;
#pragma unroll
    for (int mi = 0; mi < 4; mi++) {
        int r1 = m0 + wy * 64 + mi * 16 + g;
        int r2 = r1 + 8;
#pragma unroll
        for (int ni = 0; ni < 4; ni++) {
            int c0 = n0 + wx * 32 + ni * 8 + 2 * tg;
            float b0 = bias[c0], b1 = bias[c0 + 1];
            float v00 = (acc[mi][ni][0] + b0) * oscale, v01 = (acc[mi][ni][1] + b1) * oscale;
            float v10 = (acc[mi][ni][2] + b0) * oscale, v11 = (acc[mi][ni][3] + b1) * oscale;
            if (transHead) {
                __half* C = (__half*)Cv;
                int b_1 = r1 >> 11, l1 = r1 & 2047;
                int b_2 = r2 >> 11, l2 = r2 & 2047;
                int h = c0 >> 6, d = c0 & 63;
                *(__half2*)(C + ((size_t)(b_1 * H_ + h) * L_ + l1) * DK_ + d) = __floats2half2_rn(v00, v01);
                *(__half2*)(C + ((size_t)(b_2 * H_ + h) * L_ + l2) * DK_ + d) = __floats2half2_rn(v10, v11);
            } else {
                float* C = (float*)Cv;
                *(float2*)(C + (size_t)r1 * N + c0) = make_float2(v00, v01);
                *(float2*)(C + (size_t)r2 * N + c0) = make_float2(v10, v11);
            }
        }
    }
}

// ---- Flash attention (fp16, FA2 register softmax) --------------------------
// Block: 256 threads = 8 warps; Q tile 128 rows (warp w owns rows 16w..16w+15,
// full 64 cols). K/V tiles of 64 rows, cp.async double-buffered.
// Smem fp16 rows of 64 halves = 8 chunks of 16B, XOR-swizzled: chunk' = c ^ (r&7).

__global__ __launch_bounds__(256) void attn_fp16(
    const __half* __restrict__ Qg, const __half* __restrict__ Kg,
    const __half* __restrict__ Vg, __half* __restrict__ Og)
{
    extern __shared__ __align__(16) __half sm[];
    __half* Qs  = sm;             // 128x64 = 8192 halves
    __half* KsB = sm + 8192;      // 2 x 64x64
    __half* VsB = sm + 16384;     // 2 x 64x64

    const int tid = threadIdx.x, lane = tid & 31, w = tid >> 5;
    const int bh = blockIdx.y, qt = blockIdx.x;
    const __half* Qb = Qg + ((size_t)bh * L_ + qt * 128) * DK_;
    const __half* Kh = Kg + (size_t)bh * L_ * DK_;
    const __half* Vh = Vg + (size_t)bh * L_ * DK_;

    const uint32_t qsb = cvta_s(Qs), ksb = cvta_s(KsB), vsb = cvta_s(VsB);

#pragma unroll
    for (int i = tid; i < 1024; i += 256) {
        int r = i >> 3, c = i & 7;
        cpa16(qsb + (r * 8 + (c ^ (r & 7))) * 16, Qb + r * 64 + c * 8);
    }
#pragma unroll
    for (int i = tid; i < 512; i += 256) {
        int r = i >> 3, c = i & 7;
        uint32_t so = (r * 8 + (c ^ (r & 7))) * 16;
        cpa16(ksb + so, Kh + r * 64 + c * 8);
        cpa16(vsb + so, Vh + r * 64 + c * 8);
    }
    cpcommit();

    float m0 = -1e30f, m1 = -1e30f, l0 = 0.f, l1 = 0.f;
    float o[8][4];
#pragma unroll
    for (int i = 0; i < 8; i++)
#pragma unroll
        for (int j = 0; j < 4; j++) o[i][j] = 0.f;

    const int rlo = lane & 15, hi = lane >> 4;
    const int qrow = w * 16 + rlo;
    const uint32_t qrowb = qsb + qrow * 128;
    const int qsw = qrow & 7;

    for (int kt = 0; kt < L_ / 64; kt++) {
        cpwait0();
        __syncthreads();
        if (kt + 1 < L_ / 64) {
            int buf = (kt + 1) & 1;
            const __half* Kt = Kh + (size_t)(kt + 1) * 64 * DK_;
            const __half* Vt = Vh + (size_t)(kt + 1) * 64 * DK_;
            uint32_t kd = ksb + buf * 8192, vd = vsb + buf * 8192;
#pragma unroll
            for (int i = tid; i < 512; i += 256) {
                int r = i >> 3, c = i & 7;
                uint32_t so = (r * 8 + (c ^ (r & 7))) * 16;
                cpa16(kd + so, Kt + r * 64 + c * 8);
                cpa16(vd + so, Vt + r * 64 + c * 8);
            }
            cpcommit();
        }
        const int buf = kt & 1;
        const uint32_t kb = ksb + buf * 8192;
        const uint32_t vb = vsb + buf * 8192;

        float s[8][4];
#pragma unroll
        for (int i = 0; i < 8; i++)
#pragma unroll
            for (int j = 0; j < 4; j++) s[i][j] = 0.f;

#pragma unroll
        for (int ks = 0; ks < 4; ks++) {
            uint32_t a0, a1, a2, a3;
            ldm4(a0, a1, a2, a3, qrowb + ((2 * ks + hi) ^ qsw) * 16);
#pragma unroll
            for (int nj = 0; nj < 4; nj++) {
                int kr = nj * 16 + rlo;
                uint32_t b0, b1, b2, b3;
                ldm4(b0, b1, b2, b3, kb + kr * 128 + ((2 * ks + hi) ^ (kr & 7)) * 16);
                mma16(s[2 * nj],     a0, a1, a2, a3, b0, b2);
                mma16(s[2 * nj + 1], a0, a1, a2, a3, b1, b3);
            }
        }

        float ml0 = s[0][0], ml1 = s[0][2];
#pragma unroll
        for (int i = 0; i < 8; i++) {
            ml0 = fmaxf(ml0, fmaxf(s[i][0], s[i][1]));
            ml1 = fmaxf(ml1, fmaxf(s[i][2], s[i][3]));
        }
        ml0 = fmaxf(ml0, __shfl_xor_sync(0xffffffffu, ml0, 1));
        ml0 = fmaxf(ml0, __shfl_xor_sync(0xffffffffu, ml0, 2));
        ml1 = fmaxf(ml1, __shfl_xor_sync(0xffffffffu, ml1, 1));
        ml1 = fmaxf(ml1, __shfl_xor_sync(0xffffffffu, ml1, 2));
        float mn0 = fmaxf(m0, ml0), mn1 = fmaxf(m1, ml1);
        float c0 = ex2(m0 - mn0), c1 = ex2(m1 - mn1);
        m0 = mn0; m1 = mn1;
        float sum0 = 0.f, sum1 = 0.f;
#pragma unroll
        for (int i = 0; i < 8; i++) {
            s[i][0] = ex2(s[i][0] - mn0); s[i][1] = ex2(s[i][1] - mn0);
            s[i][2] = ex2(s[i][2] - mn1); s[i][3] = ex2(s[i][3] - mn1);
            sum0 += s[i][0] + s[i][1];
            sum1 += s[i][2] + s[i][3];
        }
        l0 = l0 * c0 + sum0;
        l1 = l1 * c1 + sum1;
#pragma unroll
        for (int i = 0; i < 8; i++) {
            o[i][0] *= c0; o[i][1] *= c0; o[i][2] *= c1; o[i][3] *= c1;
        }

#pragma unroll
        for (int ks = 0; ks < 4; ks++) {
            uint32_t a0 = h2u(__floats2half2_rn(s[2*ks][0],   s[2*ks][1]));
            uint32_t a1 = h2u(__floats2half2_rn(s[2*ks][2],   s[2*ks][3]));
            uint32_t a2 = h2u(__floats2half2_rn(s[2*ks+1][0], s[2*ks+1][1]));
            uint32_t a3 = h2u(__floats2half2_rn(s[2*ks+1][2], s[2*ks+1][3]));
            int vr = ks * 16 + rlo;
            uint32_t vrb = vb + vr * 128;
            int vsw = vr & 7;
#pragma unroll
            for (int nd = 0; nd < 4; nd++) {
                uint32_t v0, v1, v2, v3;
                ldm4t(v0, v1, v2, v3, vrb + ((2 * nd + hi) ^ vsw) * 16);
                mma16(o[2 * nd],     a0, a1, a2, a3, v0, v1);
                mma16(o[2 * nd + 1], a0, a1, a2, a3, v2, v3);
            }
        }
    }

    l0 += __shfl_xor_sync(0xffffffffu, l0, 1);
    l0 += __shfl_xor_sync(0xffffffffu, l0, 2);
    l1 += __shfl_xor_sync(0xffffffffu, l1, 1);
    l1 += __shfl_xor_sync(0xffffffffu, l1, 2);
    float inv0 = 1.f / l0, inv1 = 1.f / l1;

    const int g = lane >> 2, tg = lane & 3;
    const int b = bh >> 4, h = bh & 15;
    const int r0 = qt * 128 + w * 16 + g;
#pragma unroll
    for (int ni = 0; ni < 8; ni++) {
        int col = h * 64 + ni * 8 + 2 * tg;
        *(__half2*)(Og + (size_t)(b * L_ + r0) * D_ + col) =
            __floats2half2_rn(o[ni][0] * inv0, o[ni][1] * inv0);
        *(__half2*)(Og + (size_t)(b * L_ + r0 + 8) * D_ + col) =
            __floats2half2_rn(o[ni][2] * inv1, o[ni][3] * inv1);
    }
}

// ---------------------------------------------------------------------------

extern "C" void kernel_launch(void* const* d_in, const int* in_sizes, int n_in,
                              void* d_out, int out_size)
{
    const float* x  = (const float*)d_in[0];
    const float* wq = (const float*)d_in[1];
    const float* bq = (const float*)d_in[2];
    const float* wk = (const float*)d_in[3];
    const float* bk = (const float*)d_in[4];
    const float* wv = (const float*)d_in[5];
    const float* bv = (const float*)d_in[6];
    const float* wo = (const float*)d_in[7];
    const float* bo = (const float*)d_in[8];
    float* out = (float*)d_out;

    void *pX, *pWq, *pWk, *pWv, *pWo, *pQ, *pK, *pV, *pO;
    cudaGetSymbolAddress(&pX, g_X);
    cudaGetSymbolAddress(&pWq, g_Wq);
    cudaGetSymbolAddress(&pWk, g_Wk);
    cudaGetSymbolAddress(&pWv, g_Wv);
    cudaGetSymbolAddress(&pWo, g_Wo);
    cudaGetSymbolAddress(&pQ, g_Q);
    cudaGetSymbolAddress(&pK, g_K);
    cudaGetSymbolAddress(&pV, g_V);
    cudaGetSymbolAddress(&pO, g_O);

    const int smem_attn = (128 * 64 + 2 * 64 * 64 + 2 * 64 * 64) * sizeof(__half); // 49152
    cudaFuncSetAttribute(attn_fp16, cudaFuncAttributeMaxDynamicSharedMemorySize, smem_attn);
    cudaFuncSetAttribute(gemm_fp16, cudaFuncAttributeMaxDynamicSharedMemorySize, G_SMEM);

    // converts
    cvt_x<<<(M_ * D_) / (256 * 8), 256>>>(x, (__half*)pX);
    cvt_w<<<dim3((D_ * D_) / (256 * 8), 4), 256>>>(wq, wk, wv, wo);

    // 0.125 (Dk^-0.5) * log2(e): softmax done in base-2 domain
    const float qscale = 0.125f * 1.4426950408889634f;

    dim3 gg(D_ / 128, M_ / 128);   // (8, 32)
    gemm_fp16<<<gg, 256, G_SMEM>>>((const __half*)pX, (const __half*)pWq, bq, pQ, D_, D_, 1, qscale);
    gemm_fp16<<<gg, 256, G_SMEM>>>((const __half*)pX, (const __half*)pWk, bk, pK, D_, D_, 1, 1.0f);
    gemm_fp16<<<gg, 256, G_SMEM>>>((const __half*)pX, (const __half*)pWv, bv, pV, D_, D_, 1, 1.0f);

    attn_fp16<<<dim3(L_ / 128, B_ * H_), 256, smem_attn>>>(
        (const __half*)pQ, (const __half*)pK, (const __half*)pV, (__half*)pO);

    gemm_fp16<<<gg, 256, G_SMEM>>>((const __half*)pO, (const __half*)pWo, bo, out, D_, D_, 0, 1.0f);
}